// round 2
// baseline (speedup 1.0000x reference)
#include <cuda_runtime.h>
#include <math.h>

// Problem constants (fixed by the dataset)
#define NROW 4096          // 64*64 legality cells per board
#define QDIM 256           // quality vector length
#define NEG_FILL -1000000.0f
#define EOS_COEF 0.25f

// Global accumulators: [0]=label_sum, [1]=ce_sum, [2]=mse_sum
__device__ double g_acc[3];

__global__ void crit_init_kernel() {
    if (threadIdx.x < 3) g_acc[threadIdx.x] = 0.0;
}

// ---- block reduction helpers (256 threads, 8 warps) ----
__device__ __forceinline__ float blockReduceSum(float v, float* sh) {
    int lane = threadIdx.x & 31, warp = threadIdx.x >> 5;
    #pragma unroll
    for (int o = 16; o; o >>= 1) v += __shfl_down_sync(0xffffffffu, v, o);
    if (lane == 0) sh[warp] = v;
    __syncthreads();
    if (warp == 0) {
        v = (lane < 8) ? sh[lane] : 0.f;
        #pragma unroll
        for (int o = 4; o; o >>= 1) v += __shfl_down_sync(0xffffffffu, v, o);
        if (lane == 0) sh[0] = v;
    }
    __syncthreads();
    float r = sh[0];
    __syncthreads();
    return r;
}

__device__ __forceinline__ float blockReduceMax(float v, float* sh) {
    int lane = threadIdx.x & 31, warp = threadIdx.x >> 5;
    #pragma unroll
    for (int o = 16; o; o >>= 1) v = fmaxf(v, __shfl_down_sync(0xffffffffu, v, o));
    if (lane == 0) sh[warp] = v;
    __syncthreads();
    if (warp == 0) {
        v = (lane < 8) ? sh[lane] : -INFINITY;
        #pragma unroll
        for (int o = 4; o; o >>= 1) v = fmaxf(v, __shfl_down_sync(0xffffffffu, v, o));
        if (lane == 0) sh[0] = v;
    }
    __syncthreads();
    float r = sh[0];
    __syncthreads();
    return r;
}

// One block per batch row. 256 threads, each owning 16 contiguous cells.
__global__ __launch_bounds__(256) void crit_main_kernel(
    const float* __restrict__ pred_legal,    // [B, 4096]
    const float* __restrict__ pred_q,        // [B, 256]
    const float* __restrict__ target_legal,  // [B, 4096]
    const float* __restrict__ target_q)      // [B, 256]
{
    const int b = blockIdx.x;
    const int t = threadIdx.x;

    __shared__ float lined_sm[QDIM];
    __shared__ unsigned char match_sm[QDIM];
    __shared__ int warpT[8], warpP[8];
    __shared__ float red[8];

    const float4* pl4 = (const float4*)(pred_legal  + (size_t)b * NROW);
    const float4* tl4 = (const float4*)(target_legal + (size_t)b * NROW);

    // ---- pass 1: BCE label loss + legality bitmasks (16 bits per thread) ----
    unsigned maskT = 0u, maskP = 0u;
    float labelPart = 0.f;
    #pragma unroll
    for (int k = 0; k < 4; k++) {
        float4 pv = pl4[t * 4 + k];
        float4 tv = tl4[t * 4 + k];
        float px[4] = {pv.x, pv.y, pv.z, pv.w};
        float tx[4] = {tv.x, tv.y, tv.z, tv.w};
        #pragma unroll
        for (int j = 0; j < 4; j++) {
            float x = px[j], tg = tx[j];
            float bce = fmaxf(x, 0.f) - x * tg + log1pf(expf(-fabsf(x)));
            float w = (tg == 0.f) ? EOS_COEF : 1.f;
            labelPart += w * bce;
            int bit = k * 4 + j;
            if (tg == 1.f) maskT |= (1u << bit);
            if (x  > 0.f)  maskP |= (1u << bit);
        }
    }

    // init lined/match while scan data settles
    lined_sm[t] = NEG_FILL;
    match_sm[t] = 0;

    // ---- exclusive prefix sums of target-count / pred-count (row-major order) ----
    int cT = __popc(maskT), cP = __popc(maskP);
    int lane = t & 31, warp = t >> 5;
    int sT = cT, sP = cP; // warp-inclusive scans
    #pragma unroll
    for (int o = 1; o < 32; o <<= 1) {
        int vT = __shfl_up_sync(0xffffffffu, sT, o);
        int vP = __shfl_up_sync(0xffffffffu, sP, o);
        if (lane >= o) { sT += vT; sP += vP; }
    }
    if (lane == 31) { warpT[warp] = sT; warpP[warp] = sP; }
    __syncthreads();
    int baseT = 0, baseP = 0;
    #pragma unroll
    for (int w2 = 0; w2 < 8; w2++) {
        if (w2 < warp) { baseT += warpT[w2]; baseP += warpP[w2]; }
    }
    int tOff = baseT + sT - cT;   // exclusive target rank at my first cell
    int pOff = baseP + sP - cP;   // exclusive pred rank at my first cell

    // ---- pass 2: sparse lineup scatter (ranks are unique -> plain stores) ----
    {
        unsigned mt = maskT;
        int tIdx = tOff;
        while (mt) {
            int bit = __ffs(mt) - 1;
            mt &= mt - 1;
            if ((maskP >> bit) & 1u) {
                int pIdx = pOff + __popc(maskP & ((1u << bit) - 1u));
                // reference: valid needs p_rank < Q-1; slot Q-1 is overwritten by
                // the fixed last-slot assignment, so only keep tIdx < Q-1 too
                if (pIdx < QDIM - 1 && tIdx < QDIM - 1) {
                    lined_sm[tIdx] = __ldg(&pred_q[(size_t)b * QDIM + pIdx]);
                    match_sm[tIdx] = 1;
                }
            }
            tIdx++;
        }
    }
    __syncthreads();

    // ---- logsumexp over lined[0..254] (NEG_FILL entries underflow exactly like ref) ----
    bool active = (t < QDIM - 1);
    float linedVal = active ? lined_sm[t] : NEG_FILL;   // finite everywhere
    float mx = blockReduceMax(active ? linedVal : -INFINITY, red);
    float e  = active ? expf(linedVal - mx) : 0.f;
    float esum = blockReduceSum(e, red);
    float lse  = mx + logf(esum);

    // ---- CE terms: tn normalizer = sum of tq over columns 0..254 ONLY ----
    float m  = active ? (float)match_sm[t] : 0.f;
    float wq = active ? target_q[(size_t)b * QDIM + t] * m : 0.f;
    // linedVal is always finite, so wq==0 rows contribute exactly 0 (no 0*inf NaN)
    float dotPart = active ? wq * (linedVal - lse) : 0.f;
    float wsum = blockReduceSum(wq, red);
    float dot  = blockReduceSum(dotPart, red);
    float labelSum = blockReduceSum(labelPart, red);

    if (t == 0) {
        float ceRow = -dot / (wsum + 1e-10f);
        float dq = pred_q[(size_t)b * QDIM + (QDIM - 1)] -
                   target_q[(size_t)b * QDIM + (QDIM - 1)];
        atomicAdd(&g_acc[0], (double)labelSum);
        atomicAdd(&g_acc[1], (double)ceRow);
        atomicAdd(&g_acc[2], (double)(dq * dq));
    }
}

__global__ void crit_fin_kernel(float* __restrict__ out, int B) {
    double loss_labels = g_acc[0] / ((double)B * (double)NROW);
    double loss_ce     = g_acc[1] / (double)(QDIM - 1);
    double loss_mse    = g_acc[2] / (double)B;
    out[0] = (float)loss_labels;
    out[1] = (float)(loss_ce * 200.0 + loss_mse);
}

extern "C" void kernel_launch(void* const* d_in, const int* in_sizes, int n_in,
                              void* d_out, int out_size) {
    const float* pred_legal   = (const float*)d_in[0];
    const float* pred_q       = (const float*)d_in[1];
    const float* target_legal = (const float*)d_in[2];
    const float* target_q     = (const float*)d_in[3];
    float* out = (float*)d_out;

    int B = in_sizes[1] / QDIM;   // 4096

    crit_init_kernel<<<1, 32>>>();
    crit_main_kernel<<<B, 256>>>(pred_legal, pred_q, target_legal, target_q);
    crit_fin_kernel<<<1, 1>>>(out, B);
}